// round 16
// baseline (speedup 1.0000x reference)
#include <cuda_runtime.h>
#include <cuda_bf16.h>

#define TABLE_SCALE 1024.0f   // 2^10
#define TABLE_SIZE  4096
#define TABLE_MAX   (TABLE_SIZE - 1)
#define UNROLL 4
#define THREADS 256
#define ITER 4                      // tiles per CTA: amortizes the smem table fill
#define TILE_F4 (THREADS * UNROLL)  // 1024 float4 = 16 KB per tile

__device__ __forceinline__ int table_idx(float x) {
    int c = (int)(fabsf(x) * TABLE_SCALE);   // truncation toward zero
    return min(c, TABLE_MAX);
}

// R9 core (flat grid, U=4 front-batched .cs loads, smem table gathers,
// .cs stores) + table-fill amortization at ITER=4: each CTA processes 4
// tiles strided by gridDim (per-tile coalescing unchanged; tiles remain
// independent so the compiler can overlap tile k+1's loads under tile k's
// stores). The 16 KB smem fill is paid once per 64 KB of work instead of
// per 16 KB — measured L1 wavefront relief at ITER=2 was ~7pts and
// ~0.7 µs; this doubles the amortization again. 4096 CTAs = 3.37 waves.
__global__ void __launch_bounds__(THREADS) SecGELU_kernel(
    const float4* __restrict__ x,
    const float* __restrict__ table,
    float4* __restrict__ out,
    int n4, int tiles)
{
    __shared__ float table_s[TABLE_SIZE];

    {   // cooperative fill: 4096 floats = 1024 float4, 4 per thread
        const float4* t4 = (const float4*)table;
        float4* s4 = (float4*)table_s;
        #pragma unroll
        for (int k = 0; k < TABLE_SIZE / 4 / THREADS; k++)
            s4[threadIdx.x + k * THREADS] = t4[threadIdx.x + k * THREADS];
    }
    __syncthreads();

    #pragma unroll
    for (int it = 0; it < ITER; it++) {
        int tile = blockIdx.x + it * gridDim.x;
        if (tile >= tiles) break;
        int base = tile * TILE_F4 + threadIdx.x;

        if (base + (UNROLL - 1) * THREADS < n4) {
            float4 v[UNROLL];
            #pragma unroll
            for (int k = 0; k < UNROLL; k++)
                v[k] = __ldcs(x + base + k * THREADS);   // front-batched, independent

            float t[UNROLL][4];
            #pragma unroll
            for (int k = 0; k < UNROLL; k++) {
                t[k][0] = table_s[table_idx(v[k].x)];
                t[k][1] = table_s[table_idx(v[k].y)];
                t[k][2] = table_s[table_idx(v[k].z)];
                t[k][3] = table_s[table_idx(v[k].w)];
            }

            #pragma unroll
            for (int k = 0; k < UNROLL; k++) {
                float4 r;
                r.x = (v[k].x >= 0.0f ? v[k].x : 0.0f) - t[k][0];
                r.y = (v[k].y >= 0.0f ? v[k].y : 0.0f) - t[k][1];
                r.z = (v[k].z >= 0.0f ? v[k].z : 0.0f) - t[k][2];
                r.w = (v[k].w >= 0.0f ? v[k].w : 0.0f) - t[k][3];
                __stcs(out + base + k * THREADS, r);
            }
        } else {
            #pragma unroll
            for (int k = 0; k < UNROLL; k++) {
                int i = base + k * THREADS;
                if (i < n4) {
                    float4 v = __ldcs(x + i);
                    float4 r;
                    r.x = (v.x >= 0.0f ? v.x : 0.0f) - table_s[table_idx(v.x)];
                    r.y = (v.y >= 0.0f ? v.y : 0.0f) - table_s[table_idx(v.y)];
                    r.z = (v.z >= 0.0f ? v.z : 0.0f) - table_s[table_idx(v.z)];
                    r.w = (v.w >= 0.0f ? v.w : 0.0f) - table_s[table_idx(v.w)];
                    __stcs(out + i, r);
                }
            }
        }
    }
}

// Tail handler for n not divisible by 4 (not needed for 2^26, but safe).
__global__ void SecGELU_tail(
    const float* __restrict__ x,
    const float* __restrict__ table,
    float* __restrict__ out,
    int start, int n)
{
    int i = start + blockIdx.x * blockDim.x + threadIdx.x;
    if (i >= n) return;
    float v = x[i];
    out[i] = (v >= 0.0f ? v : 0.0f) - __ldg(table + table_idx(v));
}

extern "C" void kernel_launch(void* const* d_in, const int* in_sizes, int n_in,
                              void* d_out, int out_size) {
    const float* x     = (const float*)d_in[0];
    const float* table = (const float*)d_in[1];
    float* out = (float*)d_out;

    int n  = in_sizes[0];
    int n4 = n >> 2;

    if (n4 > 0) {
        int tiles  = (n4 + TILE_F4 - 1) / TILE_F4;
        int blocks = (tiles + ITER - 1) / ITER;
        SecGELU_kernel<<<blocks, THREADS>>>(
            (const float4*)x, table, (float4*)out, n4, tiles);
    }
    int rem = n - (n4 << 2);
    if (rem > 0) {
        SecGELU_tail<<<1, 32>>>(x, table, out, n4 << 2, n);
    }
}

// round 17
// speedup vs baseline: 1.0202x; 1.0202x over previous
#include <cuda_runtime.h>
#include <cuda_bf16.h>

#define TABLE_SCALE 1024.0f   // 2^10
#define TABLE_SIZE  4096
#define TABLE_MAX   (TABLE_SIZE - 1)
#define UNROLL 4
#define THREADS 256
#define ITER 2                      // tiles per CTA (measured optimum: 1->78.5, 2->77.8, 4->78.9)
#define TILE_F4 (THREADS * UNROLL)  // 1024 float4 = 16 KB per tile

__device__ __forceinline__ int table_idx(float x) {
    int c = (int)(fabsf(x) * TABLE_SCALE);   // truncation toward zero
    return min(c, TABLE_MAX);
}

// R15 (best kernel: 77.79us) + prologue overlap: the first tile's 4
// front-batched DRAM loads are issued BEFORE the smem table fill, so the
// fill (~250cyc L2) and the __syncthreads hide under the ~600cyc DRAM
// latency already in flight, instead of preceding it serially. Core shape
// unchanged: flat grid, U=4 .cs loads, smem table gathers, .cs stores,
// ITER=2 tiles per CTA strided by gridDim.
__global__ void __launch_bounds__(THREADS) SecGELU_kernel(
    const float4* __restrict__ x,
    const float* __restrict__ table,
    float4* __restrict__ out,
    int n4, int tiles)
{
    __shared__ float table_s[TABLE_SIZE];

    int tile0 = blockIdx.x;
    int base0 = tile0 * TILE_F4 + threadIdx.x;
    bool full0 = (base0 + (UNROLL - 1) * THREADS) < n4;

    // Issue first tile's streaming loads FIRST (independent of the table).
    float4 v0[UNROLL];
    if (full0) {
        #pragma unroll
        for (int k = 0; k < UNROLL; k++)
            v0[k] = __ldcs(x + base0 + k * THREADS);
    }

    {   // table fill hides under the in-flight DRAM loads above
        const float4* t4 = (const float4*)table;
        float4* s4 = (float4*)table_s;
        #pragma unroll
        for (int k = 0; k < TABLE_SIZE / 4 / THREADS; k++)
            s4[threadIdx.x + k * THREADS] = t4[threadIdx.x + k * THREADS];
    }
    __syncthreads();

    // ---- tile 0 ----
    if (full0) {
        float t[UNROLL][4];
        #pragma unroll
        for (int k = 0; k < UNROLL; k++) {
            t[k][0] = table_s[table_idx(v0[k].x)];
            t[k][1] = table_s[table_idx(v0[k].y)];
            t[k][2] = table_s[table_idx(v0[k].z)];
            t[k][3] = table_s[table_idx(v0[k].w)];
        }
        #pragma unroll
        for (int k = 0; k < UNROLL; k++) {
            float4 r;
            r.x = (v0[k].x >= 0.0f ? v0[k].x : 0.0f) - t[k][0];
            r.y = (v0[k].y >= 0.0f ? v0[k].y : 0.0f) - t[k][1];
            r.z = (v0[k].z >= 0.0f ? v0[k].z : 0.0f) - t[k][2];
            r.w = (v0[k].w >= 0.0f ? v0[k].w : 0.0f) - t[k][3];
            __stcs(out + base0 + k * THREADS, r);
        }
    } else if (tile0 < tiles) {
        #pragma unroll
        for (int k = 0; k < UNROLL; k++) {
            int i = base0 + k * THREADS;
            if (i < n4) {
                float4 v = __ldcs(x + i);
                float4 r;
                r.x = (v.x >= 0.0f ? v.x : 0.0f) - table_s[table_idx(v.x)];
                r.y = (v.y >= 0.0f ? v.y : 0.0f) - table_s[table_idx(v.y)];
                r.z = (v.z >= 0.0f ? v.z : 0.0f) - table_s[table_idx(v.z)];
                r.w = (v.w >= 0.0f ? v.w : 0.0f) - table_s[table_idx(v.w)];
                __stcs(out + i, r);
            }
        }
    }

    // ---- remaining tiles ----
    #pragma unroll
    for (int it = 1; it < ITER; it++) {
        int tile = blockIdx.x + it * gridDim.x;
        if (tile >= tiles) break;
        int base = tile * TILE_F4 + threadIdx.x;

        if (base + (UNROLL - 1) * THREADS < n4) {
            float4 v[UNROLL];
            #pragma unroll
            for (int k = 0; k < UNROLL; k++)
                v[k] = __ldcs(x + base + k * THREADS);   // front-batched, independent

            float t[UNROLL][4];
            #pragma unroll
            for (int k = 0; k < UNROLL; k++) {
                t[k][0] = table_s[table_idx(v[k].x)];
                t[k][1] = table_s[table_idx(v[k].y)];
                t[k][2] = table_s[table_idx(v[k].z)];
                t[k][3] = table_s[table_idx(v[k].w)];
            }

            #pragma unroll
            for (int k = 0; k < UNROLL; k++) {
                float4 r;
                r.x = (v[k].x >= 0.0f ? v[k].x : 0.0f) - t[k][0];
                r.y = (v[k].y >= 0.0f ? v[k].y : 0.0f) - t[k][1];
                r.z = (v[k].z >= 0.0f ? v[k].z : 0.0f) - t[k][2];
                r.w = (v[k].w >= 0.0f ? v[k].w : 0.0f) - t[k][3];
                __stcs(out + base + k * THREADS, r);
            }
        } else {
            #pragma unroll
            for (int k = 0; k < UNROLL; k++) {
                int i = base + k * THREADS;
                if (i < n4) {
                    float4 v = __ldcs(x + i);
                    float4 r;
                    r.x = (v.x >= 0.0f ? v.x : 0.0f) - table_s[table_idx(v.x)];
                    r.y = (v.y >= 0.0f ? v.y : 0.0f) - table_s[table_idx(v.y)];
                    r.z = (v.z >= 0.0f ? v.z : 0.0f) - table_s[table_idx(v.z)];
                    r.w = (v.w >= 0.0f ? v.w : 0.0f) - table_s[table_idx(v.w)];
                    __stcs(out + i, r);
                }
            }
        }
    }
}

// Tail handler for n not divisible by 4 (not needed for 2^26, but safe).
__global__ void SecGELU_tail(
    const float* __restrict__ x,
    const float* __restrict__ table,
    float* __restrict__ out,
    int start, int n)
{
    int i = start + blockIdx.x * blockDim.x + threadIdx.x;
    if (i >= n) return;
    float v = x[i];
    out[i] = (v >= 0.0f ? v : 0.0f) - __ldg(table + table_idx(v));
}

extern "C" void kernel_launch(void* const* d_in, const int* in_sizes, int n_in,
                              void* d_out, int out_size) {
    const float* x     = (const float*)d_in[0];
    const float* table = (const float*)d_in[1];
    float* out = (float*)d_out;

    int n  = in_sizes[0];
    int n4 = n >> 2;

    if (n4 > 0) {
        int tiles  = (n4 + TILE_F4 - 1) / TILE_F4;
        int blocks = (tiles + ITER - 1) / ITER;
        SecGELU_kernel<<<blocks, THREADS>>>(
            (const float4*)x, table, (float4*)out, n4, tiles);
    }
    int rem = n - (n4 << 2);
    if (rem > 0) {
        SecGELU_tail<<<1, 32>>>(x, table, out, n4 << 2, n);
    }
}